// round 14
// baseline (speedup 1.0000x reference)
#include <cuda_runtime.h>
#include <cstdint>

#define NP1   100001
#define BATCH 1024
#define SEQ   50
#define LBASK 20
#define HID   128

__device__ float g_X    [SEQ * BATCH * HID];
__device__ float g_gates[SEQ * BATCH * 4 * HID];   // [s][gatecol 512][batch 1024]
__device__ float g_ys   [SEQ * BATCH * HID];
__device__ float g_hidden[BATCH * 64];

__device__ __forceinline__ float tf32r(float f) {
    uint32_t u; asm("cvt.rna.tf32.f32 %0, %1;" : "=r"(u) : "f"(f));
    return __uint_as_float(u);
}
__device__ __forceinline__ float sigf(float x)  { return __fdividef(1.0f, 1.0f + __expf(-x)); }
__device__ __forceinline__ float tanh_(float x) { return __fdividef(2.0f, 1.0f + __expf(-2.0f * x)) - 1.0f; }

__device__ __forceinline__ void mma_tf32(float d[4], float a0, float a1, float a2, float a3,
                                         float b0, float b1) {
    asm volatile(
        "mma.sync.aligned.m16n8k8.row.col.f32.tf32.tf32.f32 "
        "{%0,%1,%2,%3},{%4,%5,%6,%7},{%8,%9},{%0,%1,%2,%3};"
        : "+f"(d[0]), "+f"(d[1]), "+f"(d[2]), "+f"(d[3])
        : "r"(__float_as_uint(a0)), "r"(__float_as_uint(a1)),
          "r"(__float_as_uint(a2)), "r"(__float_as_uint(a3)),
          "r"(__float_as_uint(b0)), "r"(__float_as_uint(b1)));
}
__device__ __forceinline__ uint32_t smem_u32(const void* p) {
    uint32_t a;
    asm("{ .reg .u64 t; cvta.to.shared.u64 t, %1; cvt.u32.u64 %0, t; }" : "=r"(a) : "l"(p));
    return a;
}
__device__ __forceinline__ void cluster_sync_() {
    asm volatile("barrier.cluster.arrive.aligned;\n\tbarrier.cluster.wait.aligned;" ::: "memory");
}
__device__ __forceinline__ void mbar_init(uint32_t mbar, uint32_t cnt) {
    asm volatile("mbarrier.init.shared.b64 [%0], %1;" :: "r"(mbar), "r"(cnt) : "memory");
}
__device__ __forceinline__ void mbar_expect_tx(uint32_t mbar, uint32_t bytes) {
    asm volatile("mbarrier.arrive.expect_tx.shared.b64 _, [%0], %1;"
                 :: "r"(mbar), "r"(bytes) : "memory");
}
__device__ __forceinline__ void mbar_wait(uint32_t mbar, uint32_t parity) {
    asm volatile(
        "{\n\t.reg .pred P;\n\t"
        "WAIT_%=:\n\t"
        "mbarrier.try_wait.parity.acquire.cta.shared::cta.b64 P, [%0], %1, 0x989680;\n\t"
        "@!P bra WAIT_%=;\n\t}"
        :: "r"(mbar), "r"(parity) : "memory");
}
__device__ __forceinline__ void bulk_s2s_cluster(uint32_t dst_cluster, uint32_t src_cta,
                                                 uint32_t bytes, uint32_t mbar_cluster) {
    asm volatile(
        "cp.async.bulk.shared::cluster.shared::cta.mbarrier::complete_tx::bytes [%0], [%1], %2, [%3];"
        :: "r"(dst_cluster), "r"(src_cta), "r"(bytes), "r"(mbar_cluster) : "memory");
}

// ==================== Kernel 1: featurize -> g_X[s][b][128] ====================
__global__ void __launch_bounds__(256)
featurize_kernel(const int* __restrict__ prod, const int* __restrict__ cat,
                 const float* __restrict__ age, const float* __restrict__ tsv,
                 const float* __restrict__ gender,
                 const float* __restrict__ emb_p, const float* __restrict__ emb_c,
                 const float* __restrict__ W_ts, const float* __restrict__ b_ts,
                 const float* __restrict__ W_uf, const float* __restrict__ b_uf) {
    int gid = blockIdx.x * 8 + (threadIdx.x >> 5);
    if (gid >= BATCH * SEQ) return;
    int lane = threadIdx.x & 31;
    int b = gid / SEQ, s = gid % SEQ;
    const int* pp = prod + gid * LBASK;
    const int* cc = cat  + gid * LBASK;
    float2 pa = make_float2(0.f, 0.f);
    float  ca = 0.f;
#pragma unroll 4
    for (int l = 0; l < LBASK; l++) {
        float2 v = *reinterpret_cast<const float2*>(emb_p + (size_t)pp[l] * 64 + lane * 2);
        pa.x += v.x; pa.y += v.y;
        ca += emb_c[cc[l] * 32 + lane];
    }
    float* xr = g_X + ((size_t)s * BATCH + b) * HID;
    pa.x *= (1.f / LBASK); pa.y *= (1.f / LBASK);
    *reinterpret_cast<float2*>(xr + lane * 2) = pa;
    xr[64 + lane] = ca * (1.f / LBASK);
    if (lane < 16) {
        xr[96 + lane] = W_ts[lane] * tsv[b * SEQ + s] + b_ts[lane];
    } else {
        int j = lane - 16;
        xr[112 + j] = W_uf[2 * j] * age[b] + W_uf[2 * j + 1] * gender[b] + b_uf[j];
    }
}

// ==================== Kernel 2: bulk ih-GEMM v3 (64n x 64m tiles, 3 CTAs/SM) ====================
// B strip (64n x 128k) resident; 8 m-tiles of 64 per CTA. No register pipeline —
// cross-CTA overlap (3/SM) hides load latency. Transposed vectorized epilogue.
#define BK_STRIDE 132
#define TILES_PER_CTA 8
#define BULK_SMEM_BYTES ((64 + 64) * BK_STRIDE * 4)   // 67584

__global__ void __launch_bounds__(256, 3)
bulk_gemm_kernel(const float* __restrict__ X, const float* __restrict__ Wih,
                 const float* __restrict__ bih, const float* __restrict__ bhh,
                 float* __restrict__ out) {
    extern __shared__ float sm[];
    float* Bs = sm;                       // 64 x 132, persistent
    float* As = sm + 64 * BK_STRIDE;      // 64 x 132 (aliased by Cs in epilogue)
    float* Cs = As;                       // 64 x 66 staging (n-major)
    int t = threadIdx.x;
    int n0 = blockIdx.x * 64;

    // ---- load B strip once (tf32-rounded) ----
    {
        const float4* ws = reinterpret_cast<const float4*>(Wih + (size_t)n0 * HID);
#pragma unroll
        for (int ii = 0; ii < 8; ii++) {
            int i = t + ii * 256;         // 2048 float4 = 64 x 128
            float4 w = ws[i];
            float* e = Bs + (i >> 5) * BK_STRIDE + (i & 31) * 4;
            e[0] = tf32r(w.x); e[1] = tf32r(w.y); e[2] = tf32r(w.z); e[3] = tf32r(w.w);
        }
    }

    int warp = t >> 5, lane = t & 31, g = lane >> 2, q = lane & 3;
    int wm = (warp >> 1) * 16, wn = (warp & 1) * 32;
    int mt0 = blockIdx.y * TILES_PER_CTA;
    __syncthreads();   // B ready

    for (int jj = 0; jj < TILES_PER_CTA; jj++) {
        int m0 = (mt0 + jj) * 64;

        // ---- load A tile directly (LDG -> STS) ----
        {
            const float4* xs = reinterpret_cast<const float4*>(X + (size_t)m0 * HID);
#pragma unroll
            for (int ii = 0; ii < 8; ii++) {
                int i = t + ii * 256;
                float4 v = xs[i];
                float* d = As + (i >> 5) * BK_STRIDE + (i & 31) * 4;
                d[0] = tf32r(v.x); d[1] = tf32r(v.y); d[2] = tf32r(v.z); d[3] = tf32r(v.w);
            }
        }
        __syncthreads();

        float acc[4][4];
#pragma unroll
        for (int nt = 0; nt < 4; nt++)
#pragma unroll
            for (int e = 0; e < 4; e++) acc[nt][e] = 0.f;

#pragma unroll 4
        for (int kt = 0; kt < 16; kt++) {
            int k0 = kt * 8;
            const float* Ar = As + (wm + g) * BK_STRIDE + k0 + q;
            float a0 = Ar[0];
            float a2 = Ar[4];
            float a1 = Ar[8 * BK_STRIDE];
            float a3 = Ar[8 * BK_STRIDE + 4];
#pragma unroll
            for (int nt = 0; nt < 4; nt++) {
                const float* Br = Bs + (wn + nt * 8 + g) * BK_STRIDE + k0 + q;
                mma_tf32(acc[nt], a0, a1, a2, a3, Br[0], Br[4]);
            }
        }

        // ---- epilogue: stage transposed (n-major) into Cs (aliases As) ----
        __syncthreads();
#pragma unroll
        for (int nt = 0; nt < 4; nt++) {
            int mr = wm + g;
            int nc = wn + nt * 8 + 2 * q;
            Cs[nc * 66 + mr]           = acc[nt][0];
            Cs[(nc + 1) * 66 + mr]     = acc[nt][1];
            Cs[nc * 66 + mr + 8]       = acc[nt][2];
            Cs[(nc + 1) * 66 + mr + 8] = acc[nt][3];
        }
        __syncthreads();

        int sb = m0 >> 10;
        int bb = m0 & 1023;
#pragma unroll
        for (int ii = 0; ii < 4; ii++) {
            int i4 = t + ii * 256;        // 1024 float4 = 64 cols x 64 batch
            int col = i4 >> 4, bl4 = (i4 & 15) * 4;
            int ng = n0 + col;
            float bias = bih[ng] + bhh[ng];
            const float* cr = Cs + col * 66 + bl4;
            float4 v = make_float4(cr[0] + bias, cr[1] + bias, cr[2] + bias, cr[3] + bias);
            *reinterpret_cast<float4*>(out + ((size_t)sb * 512 + ng) * 1024 + bb + bl4) = v;
        }
        __syncthreads();   // Cs reads done before next tile's STS into same region
    }
}

// ==================== Kernel 3: recurrent phase (R7/R10 protocol, FROZEN) ====================
#define TXB 4096u

__global__ void __launch_bounds__(512, 1) __cluster_dims__(2, 1, 1)
rec_kernel(const float* __restrict__ Whh, const float* __restrict__ pregates,
           const float* __restrict__ W1, const float* __restrict__ b1, int layer) {
    __shared__ __align__(16) float4 Abuf[2][512];   // 2 x 8KB, fragment-major h
    __shared__ __align__(8) unsigned long long mbar[2];

    int t = threadIdx.x;
    int w = t >> 5, lane = t & 31, g = lane >> 2, q = lane & 3;
    uint32_t r; asm("mov.u32 %0, %%cluster_ctarank;" : "=r"(r));
    int b0 = (blockIdx.x >> 1) * 16;

    float Bf[2][16][2];
#pragma unroll
    for (int nt = 0; nt < 2; nt++) {
        int grow = (nt * 2 + (g & 1)) * 128 + 64 * (int)r + 4 * w + (g >> 1);
        const float* wr = Whh + (size_t)grow * 128 + q;
#pragma unroll
        for (int kt = 0; kt < 16; kt++) {
            Bf[nt][kt][0] = tf32r(wr[kt * 8]);
            Bf[nt][kt][1] = tf32r(wr[kt * 8 + 4]);
        }
    }

#pragma unroll
    for (int i = 0; i < 2; i++) {
        int idx = t + i * 512;
        Abuf[idx >> 9][idx & 511] = make_float4(0.f, 0.f, 0.f, 0.f);
    }
    uint32_t mb0 = smem_u32(&mbar[0]);
    uint32_t mb1 = smem_u32(&mbar[1]);
    if (t == 0) {
        mbar_init(mb0, 1); mbar_init(mb1, 1);
        mbar_expect_tx(mb0, TXB);
        mbar_expect_tx(mb1, TXB);
    }
    __syncthreads();
    cluster_sync_();

    int u = 64 * (int)r + 4 * w + q;
    int bm0 = b0 + g, bm1 = b0 + g + 8;
    float c0 = 0.f, c1 = 0.f;

    uint32_t abase = smem_u32(&Abuf[0][0]);
    uint32_t hoff;
    {
        int fidx = ((u >> 3) * 8 + g) * 4 + (u & 3);
        hoff = (uint32_t)(fidx * 16 + ((u >> 2) & 1) * 8);
    }
    uint32_t peer = r ^ 1u;
    uint32_t pbase, pmb0, pmb1;
    asm("mapa.shared::cluster.u32 %0, %1, %2;" : "=r"(pbase) : "r"(abase), "r"(peer));
    asm("mapa.shared::cluster.u32 %0, %1, %2;" : "=r"(pmb0)  : "r"(mb0),   "r"(peer));
    asm("mapa.shared::cluster.u32 %0, %1, %2;" : "=r"(pmb1)  : "r"(mb1),   "r"(peer));
    uint32_t roff = (uint32_t)r * 4096u;

    size_t pgi0 = (size_t)u * 1024 + bm0;
    const float* P = pregates;
    float pg00 = P[pgi0], pg01 = P[pgi0 + 131072], pg02 = P[pgi0 + 262144], pg03 = P[pgi0 + 393216];
    float pg10 = P[pgi0 + 8], pg11 = P[pgi0 + 131080], pg12 = P[pgi0 + 262152], pg13 = P[pgi0 + 393224];

    int ph0 = 0, ph1 = 0;
    for (int s = 0; s < SEQ; s++) {
        int x = s & 1;
        if (s > 0) {
            if (x == 0) { mbar_wait(mb0, ph0); ph0 ^= 1; if (t == 0) mbar_expect_tx(mb0, TXB); }
            else        { mbar_wait(mb1, ph1); ph1 ^= 1; if (t == 0) mbar_expect_tx(mb1, TXB); }
        }

        const float4* A = Abuf[x];
        float acc[2][4];
#pragma unroll
        for (int nt = 0; nt < 2; nt++)
#pragma unroll
            for (int e = 0; e < 4; e++) acc[nt][e] = 0.f;
#pragma unroll
        for (int kt = 0; kt < 16; kt++) {
            float4 av = A[(kt * 8 + g) * 4 + q];
            mma_tf32(acc[0], av.x, av.y, av.z, av.w, Bf[0][kt][0], Bf[0][kt][1]);
            mma_tf32(acc[1], av.x, av.y, av.z, av.w, Bf[1][kt][0], Bf[1][kt][1]);
        }

        float c, h0v, h1v;
        c = sigf(acc[0][1] + pg01) * c0 + sigf(acc[0][0] + pg00) * tanh_(acc[1][0] + pg02);
        c0 = c;
        h0v = tf32r(sigf(acc[1][1] + pg03) * tanh_(c));
        c = sigf(acc[0][3] + pg11) * c1 + sigf(acc[0][2] + pg10) * tanh_(acc[1][2] + pg12);
        c1 = c;
        h1v = tf32r(sigf(acc[1][3] + pg13) * tanh_(c));

        uint64_t hp = ((uint64_t)__float_as_uint(h1v) << 32) | __float_as_uint(h0v);
        uint32_t la = abase + (uint32_t)(x ^ 1) * 8192u + hoff;
        asm volatile("st.shared.b64 [%0], %1;" :: "r"(la), "l"(hp) : "memory");

        if (layer == 0) {
            g_ys[((size_t)s * BATCH + bm0) * HID + u] = h0v;
            g_ys[((size_t)s * BATCH + bm1) * HID + u] = h1v;
        }
        __syncthreads();
        asm volatile("fence.proxy.async.shared::cta;" ::: "memory");

        if (t == 0) {
            uint32_t src = abase + (uint32_t)(x ^ 1) * 8192u + roff;
            uint32_t dst = pbase + (uint32_t)(x ^ 1) * 8192u + roff;
            uint32_t mbp = x ? pmb0 : pmb1;
            bulk_s2s_cluster(dst, src, TXB, mbp);
        }

        if (s + 1 < SEQ) {
            const float* Pn = pregates + (size_t)(s + 1) * 524288;
            pg00 = Pn[pgi0]; pg01 = Pn[pgi0 + 131072]; pg02 = Pn[pgi0 + 262144]; pg03 = Pn[pgi0 + 393216];
            pg10 = Pn[pgi0 + 8]; pg11 = Pn[pgi0 + 131080]; pg12 = Pn[pgi0 + 262152]; pg13 = Pn[pgi0 + 393224];
        }
    }

    mbar_wait(mb0, ph0);

    if (layer == 1) {
        const float* Af = reinterpret_cast<const float*>(&Abuf[0][0]);
        int m = t >> 5, j = t & 31;
        int row = 32 * (int)r + j;
        const float* wrow = W1 + row * HID;
        float sum = b1[row];
#pragma unroll 8
        for (int uu = 0; uu < HID; uu++) {
            int fi = (((uu >> 3) * 8 + (m & 7)) * 4 + (uu & 3)) * 4 + ((uu >> 2) & 1) * 2 + (m >> 3);
            sum += wrow[uu] * Af[fi];
        }
        g_hidden[(b0 + m) * 64 + row] = fmaxf(sum, 0.f);
    }
    cluster_sync_();
}

// ==================== Kernel 4: head, persistent-B over all 8 m-blocks (R13) ====================
#define HD_STRIDE 68
#define HE_STRIDE 132
#define HEAD_SMEM_BYTES (2 * 128 * HD_STRIDE * 4)   // 69632

__global__ void __launch_bounds__(256, 2)
head_kernel(const float* __restrict__ W2, const float* __restrict__ b2,
            float* __restrict__ out) {
    extern __shared__ float sm[];
    float* As = sm;                        // 128 x 68 (aliased by Cs in epilogue)
    float* Bs = sm + 128 * HD_STRIDE;      // 128 x 68, persistent
    float* Cs = As;                        // 64 x 132 half-tile staging
    int t = threadIdx.x;
    int n0 = blockIdx.x * 128;
    int warp = t >> 5, lane = t & 31, g = lane >> 2, q = lane & 3;
    int wm = (warp >> 2) * 64, wn = (warp & 3) * 32;
    bool full = (n0 + 128 <= NP1);

#pragma unroll
    for (int ii = 0; ii < 8; ii++) {
        int i = t + ii * 256;
        int rn = i >> 4;
        float4 v = make_float4(0.f, 0.f, 0.f, 0.f);
        if (n0 + rn < NP1)
            v = reinterpret_cast<const float4*>(W2 + (size_t)(n0 + rn) * 64)[i & 15];
        float* d = Bs + rn * HD_STRIDE + (i & 15) * 4;
        d[0] = tf32r(v.x); d[1] = tf32r(v.y); d[2] = tf32r(v.z); d[3] = tf32r(v.w);
    }

    for (int mb = 0; mb < 8; mb++) {
        int m0 = mb * 128;
        __syncthreads();
        {
            const float4* src = reinterpret_cast<const float4*>(g_hidden + (size_t)m0 * 64);
#pragma unroll
            for (int ii = 0; ii < 8; ii++) {
                int i = t + ii * 256;
                float4 v = src[i];
                float* d = As + (i >> 4) * HD_STRIDE + (i & 15) * 4;
                d[0] = tf32r(v.x); d[1] = tf32r(v.y); d[2] = tf32r(v.z); d[3] = tf32r(v.w);
            }
        }
        __syncthreads();

        float acc[4][4][4];
#pragma unroll
        for (int mt = 0; mt < 4; mt++)
#pragma unroll
            for (int nt = 0; nt < 4; nt++)
#pragma unroll
                for (int e = 0; e < 4; e++) acc[mt][nt][e] = 0.f;

#pragma unroll
        for (int kt = 0; kt < 8; kt++) {
            int k0 = kt * 8;
            float a[4][4];
#pragma unroll
            for (int mt = 0; mt < 4; mt++) {
                const float* Ar = As + (wm + mt * 16 + g) * HD_STRIDE + k0 + q;
                a[mt][0] = Ar[0];
                a[mt][2] = Ar[4];
                a[mt][1] = Ar[8 * HD_STRIDE];
                a[mt][3] = Ar[8 * HD_STRIDE + 4];
            }
#pragma unroll
            for (int nt = 0; nt < 4; nt++) {
                const float* Br = Bs + (wn + nt * 8 + g) * HD_STRIDE + k0 + q;
                float bv0 = Br[0], bv1 = Br[4];
#pragma unroll
                for (int mt = 0; mt < 4; mt++)
                    mma_tf32(acc[mt][nt], a[mt][0], a[mt][1], a[mt][2], a[mt][3], bv0, bv1);
            }
        }
        __syncthreads();

#pragma unroll
        for (int half = 0; half < 2; half++) {
            if ((warp >> 2) == half) {
#pragma unroll
                for (int mt = 0; mt < 4; mt++)
#pragma unroll
                    for (int nt = 0; nt < 4; nt++) {
                        int mr = mt * 16 + g;
                        int nc = wn + nt * 8 + 2 * q;
                        int ng = n0 + nc;
                        float bb0 = (ng < NP1)     ? b2[ng]     : 0.f;
                        float bb1 = (ng + 1 < NP1) ? b2[ng + 1] : 0.f;
                        Cs[mr * HE_STRIDE + nc]           = acc[mt][nt][0] + bb0;
                        Cs[mr * HE_STRIDE + nc + 1]       = acc[mt][nt][1] + bb1;
                        Cs[(mr + 8) * HE_STRIDE + nc]     = acc[mt][nt][2] + bb0;
                        Cs[(mr + 8) * HE_STRIDE + nc + 1] = acc[mt][nt][3] + bb1;
                    }
            }
            __syncthreads();

            if (full) {
#pragma unroll
                for (int rr = 0; rr < 8; rr++) {
                    int lrow = warp * 8 + rr;
                    const float* cr = Cs + lrow * HE_STRIDE;
                    size_t base = (size_t)(m0 + half * 64 + lrow) * NP1 + n0;
                    int lead = (int)((4 - (base & 3)) & 3);
                    if (lane < 31) {
                        const float* c4 = cr + lead + lane * 4;
                        *reinterpret_cast<float4*>(out + base + lead + lane * 4) =
                            make_float4(c4[0], c4[1], c4[2], c4[3]);
                    } else {
#pragma unroll
                        for (int j = 0; j < 4; j++) {
                            int pos = (j < lead) ? j : (lead + 124 + (j - lead));
                            out[base + pos] = cr[pos];
                        }
                    }
                }
            } else {
#pragma unroll
                for (int ii = 0; ii < 32; ii++) {
                    int i = t + ii * 256;
                    int lrow = i >> 7, col = i & 127;
                    int ng = n0 + col;
                    if (ng < NP1)
                        out[(size_t)(m0 + half * 64 + lrow) * NP1 + ng] =
                            Cs[lrow * HE_STRIDE + col];
                }
            }
            __syncthreads();
        }
    }
}

// ==================== launch ====================
extern "C" void kernel_launch(void* const* d_in, const int* in_sizes, int n_in,
                              void* d_out, int out_size) {
    const int*   prod   = (const int*)d_in[0];
    const int*   cat    = (const int*)d_in[1];
    const float* age    = (const float*)d_in[2];
    const float* tsv    = (const float*)d_in[3];
    const float* gender = (const float*)d_in[4];
    const float* emb_p  = (const float*)d_in[5];
    const float* emb_c  = (const float*)d_in[6];
    const float* W_ts   = (const float*)d_in[7];
    const float* b_ts   = (const float*)d_in[8];
    const float* W_uf   = (const float*)d_in[9];
    const float* b_uf   = (const float*)d_in[10];
    const float* Wih0   = (const float*)d_in[11];
    const float* Whh0   = (const float*)d_in[12];
    const float* bih0   = (const float*)d_in[13];
    const float* bhh0   = (const float*)d_in[14];
    const float* Wih1   = (const float*)d_in[15];
    const float* Whh1   = (const float*)d_in[16];
    const float* bih1   = (const float*)d_in[17];
    const float* bhh1   = (const float*)d_in[18];
    const float* W1     = (const float*)d_in[19];
    const float* b1     = (const float*)d_in[20];
    const float* W2     = (const float*)d_in[21];
    const float* b2     = (const float*)d_in[22];
    float* out = (float*)d_out;

    cudaFuncSetAttribute(bulk_gemm_kernel, cudaFuncAttributeMaxDynamicSharedMemorySize, BULK_SMEM_BYTES);
    cudaFuncSetAttribute(head_kernel, cudaFuncAttributeMaxDynamicSharedMemorySize, HEAD_SMEM_BYTES);

    float* gX = nullptr;  cudaGetSymbolAddress((void**)&gX,  g_X);
    float* gG = nullptr;  cudaGetSymbolAddress((void**)&gG,  g_gates);
    float* gY = nullptr;  cudaGetSymbolAddress((void**)&gY,  g_ys);

    featurize_kernel<<<(BATCH * SEQ + 7) / 8, 256>>>(prod, cat, age, tsv, gender,
                                                     emb_p, emb_c, W_ts, b_ts, W_uf, b_uf);
    bulk_gemm_kernel<<<dim3(8, (SEQ * BATCH / 64) / TILES_PER_CTA), 256, BULK_SMEM_BYTES>>>(
        gX, Wih0, bih0, bhh0, gG);
    rec_kernel<<<(BATCH / 16) * 2, 512>>>(Whh0, gG, W1, b1, 0);
    bulk_gemm_kernel<<<dim3(8, (SEQ * BATCH / 64) / TILES_PER_CTA), 256, BULK_SMEM_BYTES>>>(
        gY, Wih1, bih1, bhh1, gG);
    rec_kernel<<<(BATCH / 16) * 2, 512>>>(Whh1, gG, W1, b1, 1);
    head_kernel<<<(NP1 + 127) / 128, 256, HEAD_SMEM_BYTES>>>(W2, b2, out);
}

// round 15
// speedup vs baseline: 1.0777x; 1.0777x over previous
#include <cuda_runtime.h>
#include <cstdint>

#define NP1   100001
#define BATCH 1024
#define SEQ   50
#define LBASK 20
#define HID   128

__device__ float g_X    [SEQ * BATCH * HID];
__device__ float g_gates[SEQ * BATCH * 4 * HID];   // [s][gatecol 512][batch 1024]
__device__ float g_ys   [SEQ * BATCH * HID];
__device__ float g_hidden[BATCH * 64];

__device__ __forceinline__ float tf32r(float f) {
    uint32_t u; asm("cvt.rna.tf32.f32 %0, %1;" : "=r"(u) : "f"(f));
    return __uint_as_float(u);
}
__device__ __forceinline__ float tanh_hw(float x) {
    float y; asm("tanh.approx.f32 %0, %1;" : "=f"(y) : "f"(x));
    return y;
}
__device__ __forceinline__ float sig_hw(float x) {
    return fmaf(tanh_hw(0.5f * x), 0.5f, 0.5f);
}

__device__ __forceinline__ void mma_tf32(float d[4], float a0, float a1, float a2, float a3,
                                         float b0, float b1) {
    asm volatile(
        "mma.sync.aligned.m16n8k8.row.col.f32.tf32.tf32.f32 "
        "{%0,%1,%2,%3},{%4,%5,%6,%7},{%8,%9},{%0,%1,%2,%3};"
        : "+f"(d[0]), "+f"(d[1]), "+f"(d[2]), "+f"(d[3])
        : "r"(__float_as_uint(a0)), "r"(__float_as_uint(a1)),
          "r"(__float_as_uint(a2)), "r"(__float_as_uint(a3)),
          "r"(__float_as_uint(b0)), "r"(__float_as_uint(b1)));
}
__device__ __forceinline__ uint32_t smem_u32(const void* p) {
    uint32_t a;
    asm("{ .reg .u64 t; cvta.to.shared.u64 t, %1; cvt.u32.u64 %0, t; }" : "=r"(a) : "l"(p));
    return a;
}
__device__ __forceinline__ void cluster_sync_() {
    asm volatile("barrier.cluster.arrive.aligned;\n\tbarrier.cluster.wait.aligned;" ::: "memory");
}
__device__ __forceinline__ void mbar_init(uint32_t mbar, uint32_t cnt) {
    asm volatile("mbarrier.init.shared.b64 [%0], %1;" :: "r"(mbar), "r"(cnt) : "memory");
}
__device__ __forceinline__ void mbar_expect_tx(uint32_t mbar, uint32_t bytes) {
    asm volatile("mbarrier.arrive.expect_tx.shared.b64 _, [%0], %1;"
                 :: "r"(mbar), "r"(bytes) : "memory");
}
__device__ __forceinline__ void mbar_wait(uint32_t mbar, uint32_t parity) {
    asm volatile(
        "{\n\t.reg .pred P;\n\t"
        "WAIT_%=:\n\t"
        "mbarrier.try_wait.parity.acquire.cta.shared::cta.b64 P, [%0], %1, 0x989680;\n\t"
        "@!P bra WAIT_%=;\n\t}"
        :: "r"(mbar), "r"(parity) : "memory");
}
__device__ __forceinline__ void bulk_s2s_cluster(uint32_t dst_cluster, uint32_t src_cta,
                                                 uint32_t bytes, uint32_t mbar_cluster) {
    asm volatile(
        "cp.async.bulk.shared::cluster.shared::cta.mbarrier::complete_tx::bytes [%0], [%1], %2, [%3];"
        :: "r"(dst_cluster), "r"(src_cta), "r"(bytes), "r"(mbar_cluster) : "memory");
}

// ==================== Kernel 1: featurize -> g_X[s][b][128] ====================
__global__ void __launch_bounds__(256)
featurize_kernel(const int* __restrict__ prod, const int* __restrict__ cat,
                 const float* __restrict__ age, const float* __restrict__ tsv,
                 const float* __restrict__ gender,
                 const float* __restrict__ emb_p, const float* __restrict__ emb_c,
                 const float* __restrict__ W_ts, const float* __restrict__ b_ts,
                 const float* __restrict__ W_uf, const float* __restrict__ b_uf) {
    int gid = blockIdx.x * 8 + (threadIdx.x >> 5);
    if (gid >= BATCH * SEQ) return;
    int lane = threadIdx.x & 31;
    int b = gid / SEQ, s = gid % SEQ;
    const int* pp = prod + gid * LBASK;
    const int* cc = cat  + gid * LBASK;
    float2 pa = make_float2(0.f, 0.f);
    float  ca = 0.f;
#pragma unroll 4
    for (int l = 0; l < LBASK; l++) {
        float2 v = *reinterpret_cast<const float2*>(emb_p + (size_t)pp[l] * 64 + lane * 2);
        pa.x += v.x; pa.y += v.y;
        ca += emb_c[cc[l] * 32 + lane];
    }
    float* xr = g_X + ((size_t)s * BATCH + b) * HID;
    pa.x *= (1.f / LBASK); pa.y *= (1.f / LBASK);
    *reinterpret_cast<float2*>(xr + lane * 2) = pa;
    xr[64 + lane] = ca * (1.f / LBASK);
    if (lane < 16) {
        xr[96 + lane] = W_ts[lane] * tsv[b * SEQ + s] + b_ts[lane];
    } else {
        int j = lane - 16;
        xr[112 + j] = W_uf[2 * j] * age[b] + W_uf[2 * j + 1] * gender[b] + b_uf[j];
    }
}

// ==================== Kernel 2: bulk ih-GEMM (R11/R13 proven version) ====================
#define BK_STRIDE 132
#define TILES_PER_CTA 4
#define BULK_SMEM_BYTES ((128 + 64) * BK_STRIDE * 4)   // 101376

__global__ void __launch_bounds__(256, 2)
bulk_gemm_kernel(const float* __restrict__ X, const float* __restrict__ Wih,
                 const float* __restrict__ bih, const float* __restrict__ bhh,
                 float* __restrict__ out) {
    extern __shared__ float sm[];
    float* Bs = sm;                       // 128 x 132, persistent
    float* As = sm + 128 * BK_STRIDE;     // 64 x 132 (aliased by Cs in epilogue)
    float* Cs = As;                       // 128 x 66
    int t = threadIdx.x;
    int n0 = blockIdx.x * 128;

    {
        const float4* ws = reinterpret_cast<const float4*>(Wih + (size_t)n0 * HID);
#pragma unroll
        for (int ii = 0; ii < 16; ii++) {
            int i = t + ii * 256;
            float4 w = ws[i];
            float* e = Bs + (i >> 5) * BK_STRIDE + (i & 31) * 4;
            e[0] = tf32r(w.x); e[1] = tf32r(w.y); e[2] = tf32r(w.z); e[3] = tf32r(w.w);
        }
    }

    int warp = t >> 5, lane = t & 31, g = lane >> 2, q = lane & 3;
    int wm = (warp >> 2) * 32, wn = (warp & 3) * 32;

    int mt0 = blockIdx.y * TILES_PER_CTA;
    float4 areg[8];
    {
        const float4* xs = reinterpret_cast<const float4*>(X + (size_t)mt0 * 64 * HID);
#pragma unroll
        for (int ii = 0; ii < 8; ii++) areg[ii] = xs[t + ii * 256];
    }
    __syncthreads();   // B ready

    for (int jj = 0; jj < TILES_PER_CTA; jj++) {
        int m0 = (mt0 + jj) * 64;

#pragma unroll
        for (int ii = 0; ii < 8; ii++) {
            int i = t + ii * 256;
            float* d = As + (i >> 5) * BK_STRIDE + (i & 31) * 4;
            d[0] = tf32r(areg[ii].x); d[1] = tf32r(areg[ii].y);
            d[2] = tf32r(areg[ii].z); d[3] = tf32r(areg[ii].w);
        }
        __syncthreads();

        if (jj + 1 < TILES_PER_CTA) {
            const float4* xs = reinterpret_cast<const float4*>(X + (size_t)(mt0 + jj + 1) * 64 * HID);
#pragma unroll
            for (int ii = 0; ii < 8; ii++) areg[ii] = xs[t + ii * 256];
        }

        float acc[2][4][4];
#pragma unroll
        for (int mt = 0; mt < 2; mt++)
#pragma unroll
            for (int nt = 0; nt < 4; nt++)
#pragma unroll
                for (int e = 0; e < 4; e++) acc[mt][nt][e] = 0.f;

#pragma unroll 4
        for (int kt = 0; kt < 16; kt++) {
            int k0 = kt * 8;
            float a[2][4];
#pragma unroll
            for (int mt = 0; mt < 2; mt++) {
                const float* Ar = As + (wm + mt * 16 + g) * BK_STRIDE + k0 + q;
                a[mt][0] = Ar[0];
                a[mt][2] = Ar[4];
                a[mt][1] = Ar[8 * BK_STRIDE];
                a[mt][3] = Ar[8 * BK_STRIDE + 4];
            }
#pragma unroll
            for (int nt = 0; nt < 4; nt++) {
                const float* Br = Bs + (wn + nt * 8 + g) * BK_STRIDE + k0 + q;
                float bv0 = Br[0], bv1 = Br[4];
                mma_tf32(acc[0][nt], a[0][0], a[0][1], a[0][2], a[0][3], bv0, bv1);
                mma_tf32(acc[1][nt], a[1][0], a[1][1], a[1][2], a[1][3], bv0, bv1);
            }
        }

        __syncthreads();
#pragma unroll
        for (int mt = 0; mt < 2; mt++)
#pragma unroll
            for (int nt = 0; nt < 4; nt++) {
                int mr = wm + mt * 16 + g;
                int nc = wn + nt * 8 + 2 * q;
                Cs[nc * 66 + mr]           = acc[mt][nt][0];
                Cs[(nc + 1) * 66 + mr]     = acc[mt][nt][1];
                Cs[nc * 66 + mr + 8]       = acc[mt][nt][2];
                Cs[(nc + 1) * 66 + mr + 8] = acc[mt][nt][3];
            }
        __syncthreads();

        int sb = m0 >> 10;
        int bb = m0 & 1023;
#pragma unroll
        for (int ii = 0; ii < 8; ii++) {
            int i4 = t + ii * 256;
            int col = i4 >> 4, bl4 = (i4 & 15) * 4;
            int ng = n0 + col;
            float bias = bih[ng] + bhh[ng];
            const float* cr = Cs + col * 66 + bl4;
            float4 v = make_float4(cr[0] + bias, cr[1] + bias, cr[2] + bias, cr[3] + bias);
            *reinterpret_cast<float4*>(out + ((size_t)sb * 512 + ng) * 1024 + bb + bl4) = v;
        }
        __syncthreads();
    }
}

// ==================== Kernel 3: recurrent phase (R7 protocol FROZEN; HW tanh) ====================
#define TXB 4096u

__global__ void __launch_bounds__(512, 1) __cluster_dims__(2, 1, 1)
rec_kernel(const float* __restrict__ Whh, const float* __restrict__ pregates,
           const float* __restrict__ W1, const float* __restrict__ b1, int layer) {
    __shared__ __align__(16) float4 Abuf[2][512];   // 2 x 8KB, fragment-major h
    __shared__ __align__(8) unsigned long long mbar[2];

    int t = threadIdx.x;
    int w = t >> 5, lane = t & 31, g = lane >> 2, q = lane & 3;
    uint32_t r; asm("mov.u32 %0, %%cluster_ctarank;" : "=r"(r));
    int b0 = (blockIdx.x >> 1) * 16;

    float Bf[2][16][2];
#pragma unroll
    for (int nt = 0; nt < 2; nt++) {
        int grow = (nt * 2 + (g & 1)) * 128 + 64 * (int)r + 4 * w + (g >> 1);
        const float* wr = Whh + (size_t)grow * 128 + q;
#pragma unroll
        for (int kt = 0; kt < 16; kt++) {
            Bf[nt][kt][0] = tf32r(wr[kt * 8]);
            Bf[nt][kt][1] = tf32r(wr[kt * 8 + 4]);
        }
    }

#pragma unroll
    for (int i = 0; i < 2; i++) {
        int idx = t + i * 512;
        Abuf[idx >> 9][idx & 511] = make_float4(0.f, 0.f, 0.f, 0.f);
    }
    uint32_t mb0 = smem_u32(&mbar[0]);
    uint32_t mb1 = smem_u32(&mbar[1]);
    if (t == 0) {
        mbar_init(mb0, 1); mbar_init(mb1, 1);
        mbar_expect_tx(mb0, TXB);
        mbar_expect_tx(mb1, TXB);
    }
    __syncthreads();
    cluster_sync_();

    int u = 64 * (int)r + 4 * w + q;
    int bm0 = b0 + g, bm1 = b0 + g + 8;
    float c0 = 0.f, c1 = 0.f;

    uint32_t abase = smem_u32(&Abuf[0][0]);
    uint32_t hoff;
    {
        int fidx = ((u >> 3) * 8 + g) * 4 + (u & 3);
        hoff = (uint32_t)(fidx * 16 + ((u >> 2) & 1) * 8);
    }
    uint32_t peer = r ^ 1u;
    uint32_t pbase, pmb0, pmb1;
    asm("mapa.shared::cluster.u32 %0, %1, %2;" : "=r"(pbase) : "r"(abase), "r"(peer));
    asm("mapa.shared::cluster.u32 %0, %1, %2;" : "=r"(pmb0)  : "r"(mb0),   "r"(peer));
    asm("mapa.shared::cluster.u32 %0, %1, %2;" : "=r"(pmb1)  : "r"(mb1),   "r"(peer));
    uint32_t roff = (uint32_t)r * 4096u;

    size_t pgi0 = (size_t)u * 1024 + bm0;
    const float* P = pregates;
    float pg00 = P[pgi0], pg01 = P[pgi0 + 131072], pg02 = P[pgi0 + 262144], pg03 = P[pgi0 + 393216];
    float pg10 = P[pgi0 + 8], pg11 = P[pgi0 + 131080], pg12 = P[pgi0 + 262152], pg13 = P[pgi0 + 393224];

    int ph0 = 0, ph1 = 0;
    for (int s = 0; s < SEQ; s++) {
        int x = s & 1;
        if (s > 0) {
            if (x == 0) { mbar_wait(mb0, ph0); ph0 ^= 1; if (t == 0) mbar_expect_tx(mb0, TXB); }
            else        { mbar_wait(mb1, ph1); ph1 ^= 1; if (t == 0) mbar_expect_tx(mb1, TXB); }
        }

        const float4* A = Abuf[x];
        float acc[2][4];
#pragma unroll
        for (int nt = 0; nt < 2; nt++)
#pragma unroll
            for (int e = 0; e < 4; e++) acc[nt][e] = 0.f;
#pragma unroll
        for (int kt = 0; kt < 16; kt++) {
            float4 av = A[(kt * 8 + g) * 4 + q];
            mma_tf32(acc[0], av.x, av.y, av.z, av.w, Bf[0][kt][0], Bf[0][kt][1]);
            mma_tf32(acc[1], av.x, av.y, av.z, av.w, Bf[1][kt][0], Bf[1][kt][1]);
        }

        // cell update (HW tanh.approx; sig(x) = 0.5*tanh(x/2)+0.5)
        float c, h0v, h1v;
        c = sig_hw(acc[0][1] + pg01) * c0 + sig_hw(acc[0][0] + pg00) * tanh_hw(acc[1][0] + pg02);
        c0 = c;
        h0v = tf32r(sig_hw(acc[1][1] + pg03) * tanh_hw(c));
        c = sig_hw(acc[0][3] + pg11) * c1 + sig_hw(acc[0][2] + pg10) * tanh_hw(acc[1][2] + pg12);
        c1 = c;
        h1v = tf32r(sig_hw(acc[1][3] + pg13) * tanh_hw(c));

        uint64_t hp = ((uint64_t)__float_as_uint(h1v) << 32) | __float_as_uint(h0v);
        uint32_t la = abase + (uint32_t)(x ^ 1) * 8192u + hoff;
        asm volatile("st.shared.b64 [%0], %1;" :: "r"(la), "l"(hp) : "memory");

        if (layer == 0) {
            g_ys[((size_t)s * BATCH + bm0) * HID + u] = h0v;
            g_ys[((size_t)s * BATCH + bm1) * HID + u] = h1v;
        }
        __syncthreads();
        asm volatile("fence.proxy.async.shared::cta;" ::: "memory");

        if (t == 0) {
            uint32_t src = abase + (uint32_t)(x ^ 1) * 8192u + roff;
            uint32_t dst = pbase + (uint32_t)(x ^ 1) * 8192u + roff;
            uint32_t mbp = x ? pmb0 : pmb1;
            bulk_s2s_cluster(dst, src, TXB, mbp);
        }

        if (s + 1 < SEQ) {
            const float* Pn = pregates + (size_t)(s + 1) * 524288;
            pg00 = Pn[pgi0]; pg01 = Pn[pgi0 + 131072]; pg02 = Pn[pgi0 + 262144]; pg03 = Pn[pgi0 + 393216];
            pg10 = Pn[pgi0 + 8]; pg11 = Pn[pgi0 + 131080]; pg12 = Pn[pgi0 + 262152]; pg13 = Pn[pgi0 + 393224];
        }
    }

    mbar_wait(mb0, ph0);

    if (layer == 1) {
        const float* Af = reinterpret_cast<const float*>(&Abuf[0][0]);
        int m = t >> 5, j = t & 31;
        int row = 32 * (int)r + j;
        const float* wrow = W1 + row * HID;
        float sum = b1[row];
#pragma unroll 8
        for (int uu = 0; uu < HID; uu++) {
            int fi = (((uu >> 3) * 8 + (m & 7)) * 4 + (uu & 3)) * 4 + ((uu >> 2) & 1) * 2 + (m >> 3);
            sum += wrow[uu] * Af[fi];
        }
        g_hidden[(b0 + m) * 64 + row] = fmaxf(sum, 0.f);
    }
    cluster_sync_();
}

// ==================== Kernel 4: head, persistent-B over all 8 m-blocks (R13) ====================
#define HD_STRIDE 68
#define HE_STRIDE 132
#define HEAD_SMEM_BYTES (2 * 128 * HD_STRIDE * 4)   // 69632

__global__ void __launch_bounds__(256, 2)
head_kernel(const float* __restrict__ W2, const float* __restrict__ b2,
            float* __restrict__ out) {
    extern __shared__ float sm[];
    float* As = sm;
    float* Bs = sm + 128 * HD_STRIDE;
    float* Cs = As;
    int t = threadIdx.x;
    int n0 = blockIdx.x * 128;
    int warp = t >> 5, lane = t & 31, g = lane >> 2, q = lane & 3;
    int wm = (warp >> 2) * 64, wn = (warp & 3) * 32;
    bool full = (n0 + 128 <= NP1);

#pragma unroll
    for (int ii = 0; ii < 8; ii++) {
        int i = t + ii * 256;
        int rn = i >> 4;
        float4 v = make_float4(0.f, 0.f, 0.f, 0.f);
        if (n0 + rn < NP1)
            v = reinterpret_cast<const float4*>(W2 + (size_t)(n0 + rn) * 64)[i & 15];
        float* d = Bs + rn * HD_STRIDE + (i & 15) * 4;
        d[0] = tf32r(v.x); d[1] = tf32r(v.y); d[2] = tf32r(v.z); d[3] = tf32r(v.w);
    }

    for (int mb = 0; mb < 8; mb++) {
        int m0 = mb * 128;
        __syncthreads();
        {
            const float4* src = reinterpret_cast<const float4*>(g_hidden + (size_t)m0 * 64);
#pragma unroll
            for (int ii = 0; ii < 8; ii++) {
                int i = t + ii * 256;
                float4 v = src[i];
                float* d = As + (i >> 4) * HD_STRIDE + (i & 15) * 4;
                d[0] = tf32r(v.x); d[1] = tf32r(v.y); d[2] = tf32r(v.z); d[3] = tf32r(v.w);
            }
        }
        __syncthreads();

        float acc[4][4][4];
#pragma unroll
        for (int mt = 0; mt < 4; mt++)
#pragma unroll
            for (int nt = 0; nt < 4; nt++)
#pragma unroll
                for (int e = 0; e < 4; e++) acc[mt][nt][e] = 0.f;

#pragma unroll
        for (int kt = 0; kt < 8; kt++) {
            int k0 = kt * 8;
            float a[4][4];
#pragma unroll
            for (int mt = 0; mt < 4; mt++) {
                const float* Ar = As + (wm + mt * 16 + g) * HD_STRIDE + k0 + q;
                a[mt][0] = Ar[0];
                a[mt][2] = Ar[4];
                a[mt][1] = Ar[8 * HD_STRIDE];
                a[mt][3] = Ar[8 * HD_STRIDE + 4];
            }
#pragma unroll
            for (int nt = 0; nt < 4; nt++) {
                const float* Br = Bs + (wn + nt * 8 + g) * HD_STRIDE + k0 + q;
                float bv0 = Br[0], bv1 = Br[4];
#pragma unroll
                for (int mt = 0; mt < 4; mt++)
                    mma_tf32(acc[mt][nt], a[mt][0], a[mt][1], a[mt][2], a[mt][3], bv0, bv1);
            }
        }
        __syncthreads();

#pragma unroll
        for (int half = 0; half < 2; half++) {
            if ((warp >> 2) == half) {
#pragma unroll
                for (int mt = 0; mt < 4; mt++)
#pragma unroll
                    for (int nt = 0; nt < 4; nt++) {
                        int mr = mt * 16 + g;
                        int nc = wn + nt * 8 + 2 * q;
                        int ng = n0 + nc;
                        float bb0 = (ng < NP1)     ? b2[ng]     : 0.f;
                        float bb1 = (ng + 1 < NP1) ? b2[ng + 1] : 0.f;
                        Cs[mr * HE_STRIDE + nc]           = acc[mt][nt][0] + bb0;
                        Cs[mr * HE_STRIDE + nc + 1]       = acc[mt][nt][1] + bb1;
                        Cs[(mr + 8) * HE_STRIDE + nc]     = acc[mt][nt][2] + bb0;
                        Cs[(mr + 8) * HE_STRIDE + nc + 1] = acc[mt][nt][3] + bb1;
                    }
            }
            __syncthreads();

            if (full) {
#pragma unroll
                for (int rr = 0; rr < 8; rr++) {
                    int lrow = warp * 8 + rr;
                    const float* cr = Cs + lrow * HE_STRIDE;
                    size_t base = (size_t)(m0 + half * 64 + lrow) * NP1 + n0;
                    int lead = (int)((4 - (base & 3)) & 3);
                    if (lane < 31) {
                        const float* c4 = cr + lead + lane * 4;
                        *reinterpret_cast<float4*>(out + base + lead + lane * 4) =
                            make_float4(c4[0], c4[1], c4[2], c4[3]);
                    } else {
#pragma unroll
                        for (int j = 0; j < 4; j++) {
                            int pos = (j < lead) ? j : (lead + 124 + (j - lead));
                            out[base + pos] = cr[pos];
                        }
                    }
                }
            } else {
#pragma unroll
                for (int ii = 0; ii < 32; ii++) {
                    int i = t + ii * 256;
                    int lrow = i >> 7, col = i & 127;
                    int ng = n0 + col;
                    if (ng < NP1)
                        out[(size_t)(m0 + half * 64 + lrow) * NP1 + ng] =
                            Cs[lrow * HE_STRIDE + col];
                }
            }
            __syncthreads();
        }
    }
}

// ==================== launch ====================
extern "C" void kernel_launch(void* const* d_in, const int* in_sizes, int n_in,
                              void* d_out, int out_size) {
    const int*   prod   = (const int*)d_in[0];
    const int*   cat    = (const int*)d_in[1];
    const float* age    = (const float*)d_in[2];
    const float* tsv    = (const float*)d_in[3];
    const float* gender = (const float*)d_in[4];
    const float* emb_p  = (const float*)d_in[5];
    const float* emb_c  = (const float*)d_in[6];
    const float* W_ts   = (const float*)d_in[7];
    const float* b_ts   = (const float*)d_in[8];
    const float* W_uf   = (const float*)d_in[9];
    const float* b_uf   = (const float*)d_in[10];
    const float* Wih0   = (const float*)d_in[11];
    const float* Whh0   = (const float*)d_in[12];
    const float* bih0   = (const float*)d_in[13];
    const float* bhh0   = (const float*)d_in[14];
    const float* Wih1   = (const float*)d_in[15];
    const float* Whh1   = (const float*)d_in[16];
    const float* bih1   = (const float*)d_in[17];
    const float* bhh1   = (const float*)d_in[18];
    const float* W1     = (const float*)d_in[19];
    const float* b1     = (const float*)d_in[20];
    const float* W2     = (const float*)d_in[21];
    const float* b2     = (const float*)d_in[22];
    float* out = (float*)d_out;

    cudaFuncSetAttribute(bulk_gemm_kernel, cudaFuncAttributeMaxDynamicSharedMemorySize, BULK_SMEM_BYTES);
    cudaFuncSetAttribute(head_kernel, cudaFuncAttributeMaxDynamicSharedMemorySize, HEAD_SMEM_BYTES);

    float* gX = nullptr;  cudaGetSymbolAddress((void**)&gX,  g_X);
    float* gG = nullptr;  cudaGetSymbolAddress((void**)&gG,  g_gates);
    float* gY = nullptr;  cudaGetSymbolAddress((void**)&gY,  g_ys);

    featurize_kernel<<<(BATCH * SEQ + 7) / 8, 256>>>(prod, cat, age, tsv, gender,
                                                     emb_p, emb_c, W_ts, b_ts, W_uf, b_uf);
    bulk_gemm_kernel<<<dim3(4, (SEQ * BATCH / 64) / TILES_PER_CTA), 256, BULK_SMEM_BYTES>>>(
        gX, Wih0, bih0, bhh0, gG);
    rec_kernel<<<(BATCH / 16) * 2, 512>>>(Whh0, gG, W1, b1, 0);
    bulk_gemm_kernel<<<dim3(4, (SEQ * BATCH / 64) / TILES_PER_CTA), 256, BULK_SMEM_BYTES>>>(
        gY, Wih1, bih1, bhh1, gG);
    rec_kernel<<<(BATCH / 16) * 2, 512>>>(Whh1, gG, W1, b1, 1);
    head_kernel<<<(NP1 + 127) / 128, 256, HEAD_SMEM_BYTES>>>(W2, b2, out);
}